// round 1
// baseline (speedup 1.0000x reference)
#include <cuda_runtime.h>
#include <cuda_bf16.h>

// UltraTinyGRU fused kernel.
// B=4096 batch rows, T=512 steps, F=16 features, H=4 hidden.
// 4 threads per batch row: thread j owns gate components {j, 4+j, 8+j}
// (PyTorch gate order r,z,n). Full h (4 floats) replicated per thread via
// quad shuffles each step. x streamed with a 4-deep register prefetch.

#define GRU_T 512
#define GRU_F 16
#define GRU_H 4

__device__ __forceinline__ float fast_sigmoid(float x) {
    // 1/(1+e^-x) via MUFU.EX2 + MUFU.RCP
    float e = __expf(-x);
    return __fdividef(1.0f, 1.0f + e);
}

__device__ __forceinline__ float fast_tanh(float x) {
    // (1-e^-2x)/(1+e^-2x)
    float e = __expf(-2.0f * x);
    return __fdividef(1.0f - e, 1.0f + e);
}

__global__ __launch_bounds__(128, 1)
void ultratiny_gru_kernel(const float* __restrict__ x,
                          const float* __restrict__ w_ih,
                          const float* __restrict__ w_hh,
                          const float* __restrict__ b_ih,
                          const float* __restrict__ b_hh,
                          const float* __restrict__ fc_w,
                          const float* __restrict__ fc_b,
                          float* __restrict__ out,
                          int B) {
    const int tid = blockIdx.x * blockDim.x + threadIdx.x;
    const int b = tid >> 2;       // batch row
    const int j = tid & 3;        // owned hidden component 0..3
    if (b >= B) return;

    // ---- load weights into registers (one-time, L1/L2 broadcast) ----
    // gate rows: r=j, z=4+j, n=8+j
    float wr[GRU_F], wz[GRU_F], wn[GRU_F];
#pragma unroll
    for (int k = 0; k < GRU_F; k++) {
        wr[k] = __ldg(&w_ih[(j)     * GRU_F + k]);
        wz[k] = __ldg(&w_ih[(4 + j) * GRU_F + k]);
        wn[k] = __ldg(&w_ih[(8 + j) * GRU_F + k]);
    }
    float whr[GRU_H], whz[GRU_H], whn[GRU_H];
#pragma unroll
    for (int k = 0; k < GRU_H; k++) {
        whr[k] = __ldg(&w_hh[(j)     * GRU_H + k]);
        whz[k] = __ldg(&w_hh[(4 + j) * GRU_H + k]);
        whn[k] = __ldg(&w_hh[(8 + j) * GRU_H + k]);
    }
    // biases: r/z gates can fold b_ih+b_hh; n gate must keep them split
    const float br  = __ldg(&b_ih[j])     + __ldg(&b_hh[j]);
    const float bz  = __ldg(&b_ih[4 + j]) + __ldg(&b_hh[4 + j]);
    const float bin = __ldg(&b_ih[8 + j]);   // input-side n bias
    const float bhn = __ldg(&b_hh[8 + j]);   // hidden-side n bias

    const float* xb = x + (size_t)b * (GRU_T * GRU_F);

    // ---- 4-deep prefetch buffer for the x stream ----
    float4 buf[4][4];
#pragma unroll
    for (int i = 0; i < 4; i++) {
        const float4* p = (const float4*)(xb + i * GRU_F);
        buf[i][0] = __ldcs(p + 0);
        buf[i][1] = __ldcs(p + 1);
        buf[i][2] = __ldcs(p + 2);
        buf[i][3] = __ldcs(p + 3);
    }

    float h0 = 0.f, h1 = 0.f, h2 = 0.f, h3 = 0.f;  // replicated hidden state

    for (int tb = 0; tb < GRU_T; tb += 4) {
#pragma unroll
        for (int u = 0; u < 4; u++) {
            const int t = tb + u;
            // snapshot current timestep
            float4 c0 = buf[u][0], c1 = buf[u][1], c2 = buf[u][2], c3 = buf[u][3];
            // prefetch t+4 (clamped; duplicate last-row loads are harmless)
            int tn = t + 4;
            if (tn > GRU_T - 1) tn = GRU_T - 1;
            {
                const float4* p = (const float4*)(xb + (size_t)tn * GRU_F);
                buf[u][0] = __ldcs(p + 0);
                buf[u][1] = __ldcs(p + 1);
                buf[u][2] = __ldcs(p + 2);
                buf[u][3] = __ldcs(p + 3);
            }

            const float xv[GRU_F] = {c0.x, c0.y, c0.z, c0.w,
                                     c1.x, c1.y, c1.z, c1.w,
                                     c2.x, c2.y, c2.z, c2.w,
                                     c3.x, c3.y, c3.z, c3.w};

            // input-side gate dots (includes folded biases for r/z)
            float gr = br, gz = bz, gn = bin;
#pragma unroll
            for (int k = 0; k < GRU_F; k++) {
                gr = fmaf(xv[k], wr[k], gr);
                gz = fmaf(xv[k], wz[k], gz);
                gn = fmaf(xv[k], wn[k], gn);
            }

            // hidden-side dots (tree-shaped: shorter dependency chain)
            float ghr = (h0 * whr[0] + h1 * whr[1]) + (h2 * whr[2] + h3 * whr[3]);
            float ghz = (h0 * whz[0] + h1 * whz[1]) + (h2 * whz[2] + h3 * whz[3]);
            float ghn = (h0 * whn[0] + h1 * whn[1]) + (h2 * whn[2] + h3 * whn[3]) + bhn;

            float r = fast_sigmoid(gr + ghr);
            float z = fast_sigmoid(gz + ghz);
            float n = fast_tanh(fmaf(r, ghn, gn));

            // my component of h_new: (1-z)*n + z*h_j  ==  n + z*(h_j - n)
            float hj = (j == 0) ? h0 : (j == 1) ? h1 : (j == 2) ? h2 : h3;
            float hn = fmaf(z, hj - n, n);

            // replicate new h across the quad
            h0 = __shfl_sync(0xffffffffu, hn, 0, 4);
            h1 = __shfl_sync(0xffffffffu, hn, 1, 4);
            h2 = __shfl_sync(0xffffffffu, hn, 2, 4);
            h3 = __shfl_sync(0xffffffffu, hn, 3, 4);
        }
    }

    if (j == 0) {
        float fw0 = __ldg(&fc_w[0]), fw1 = __ldg(&fc_w[1]);
        float fw2 = __ldg(&fc_w[2]), fw3 = __ldg(&fc_w[3]);
        float o = (h0 * fw0 + h1 * fw1) + (h2 * fw2 + h3 * fw3) + __ldg(&fc_b[0]);
        out[b] = o;
    }
}

extern "C" void kernel_launch(void* const* d_in, const int* in_sizes, int n_in,
                              void* d_out, int out_size) {
    const float* x    = (const float*)d_in[0];
    const float* w_ih = (const float*)d_in[1];
    const float* w_hh = (const float*)d_in[2];
    const float* b_ih = (const float*)d_in[3];
    const float* b_hh = (const float*)d_in[4];
    const float* fc_w = (const float*)d_in[5];
    const float* fc_b = (const float*)d_in[6];
    float* out = (float*)d_out;

    const int B = out_size;                 // one output per batch row
    const int threads = 128;                // 4 warps/block -> 1 warp per SMSP
    const int total = B * 4;                // 4 threads per batch row
    const int blocks = (total + threads - 1) / threads;

    ultratiny_gru_kernel<<<blocks, threads>>>(x, w_ih, w_hh, b_ih, b_hh,
                                              fc_w, fc_b, out, B);
}